// round 1
// baseline (speedup 1.0000x reference)
#include <cuda_runtime.h>

typedef unsigned long long ull;

#define NB 8
#define NP 256
#define NH 16
#define NDK 64
#define NV 8192
#define NDM 1024
#define NDL 4096

// Scratch (device globals: allocation-free per harness rules)
__device__ float g_q[NB * NP * NDM];   // 8 MB
__device__ float g_k[NV * NDM];        // 32 MB
__device__ float g_v[NV * NDM];        // 32 MB
__device__ float g_m[NB * NP * NDM];   // 8 MB

// ---- packed fp32x2 helpers (Blackwell sm_103a) ----
__device__ __forceinline__ ull pack2(float x, float y) {
    ull r;
    asm("mov.b64 %0, {%1, %2};" : "=l"(r)
        : "r"(__float_as_uint(x)), "r"(__float_as_uint(y)));
    return r;
}
__device__ __forceinline__ float2 unpack2(ull v) {
    unsigned lo, hi;
    asm("mov.b64 {%0, %1}, %2;" : "=r"(lo), "=r"(hi) : "l"(v));
    return make_float2(__uint_as_float(lo), __uint_as_float(hi));
}
#define FMA2(acc, a, b) \
    asm("fma.rn.f32x2 %0, %1, %2, %0;" : "+l"(acc) : "l"(a), "l"(b))

// ============================================================
// SGEMM: C[M,N] = A[M,K] @ B[K,N] + bias[N]
// BM=BN=128, BK=16, 256 threads, 8x8 per-thread tile,
// inner product via packed fma.rn.f32x2 (2 cols per op).
// Requires M%128==0, N%128==0, K%16==0 (true for all calls).
// ============================================================
__global__ __launch_bounds__(256) void sgemm_bias(
    const float* __restrict__ A, const float* __restrict__ Bm,
    const float* __restrict__ bias, float* __restrict__ C,
    int M, int N, int K)
{
    __shared__ __align__(16) float As[16][132];  // transposed A tile, padded
    __shared__ __align__(16) float Bs[16][128];

    const int tid = threadIdx.x;
    const int tx = tid & 15;        // 16 cols of threads -> 8 C-cols each
    const int ty = tid >> 4;        // 16 rows of threads -> 8 C-rows each
    const int row0 = blockIdx.y * 128;
    const int col0 = blockIdx.x * 128;

    ull acc2[8][4];
#pragma unroll
    for (int m = 0; m < 8; m++)
#pragma unroll
        for (int n2 = 0; n2 < 4; n2++) acc2[m][n2] = 0ull;

    for (int k0 = 0; k0 < K; k0 += 16) {
        // Load A tile [128 x 16] -> transposed into As[k][row]
#pragma unroll
        for (int i = 0; i < 2; i++) {
            int f4 = tid + i * 256;            // 0..511
            int r  = f4 >> 2;                  // 0..127
            int kc = (f4 & 3) * 4;             // 0,4,8,12
            float4 av = *(const float4*)(A + (size_t)(row0 + r) * K + k0 + kc);
            As[kc + 0][r] = av.x; As[kc + 1][r] = av.y;
            As[kc + 2][r] = av.z; As[kc + 3][r] = av.w;
        }
        // Load B tile [16 x 128] natural layout
#pragma unroll
        for (int i = 0; i < 2; i++) {
            int f4 = tid + i * 256;
            int kr = f4 >> 5;                  // 0..15
            int c  = (f4 & 31) * 4;            // 0..124
            *(float4*)(&Bs[kr][c]) =
                *(const float4*)(Bm + (size_t)(k0 + kr) * N + col0 + c);
        }
        __syncthreads();

#pragma unroll
        for (int kk = 0; kk < 16; kk++) {
            float4 alo = *(const float4*)(&As[kk][ty * 8]);
            float4 ahi = *(const float4*)(&As[kk][ty * 8 + 4]);
            float a[8] = {alo.x, alo.y, alo.z, alo.w,
                          ahi.x, ahi.y, ahi.z, ahi.w};
            ull b2[4];
#pragma unroll
            for (int n2 = 0; n2 < 4; n2++)
                b2[n2] = *(const ull*)(&Bs[kk][tx * 8 + n2 * 2]);
#pragma unroll
            for (int m = 0; m < 8; m++) {
                ull a2 = pack2(a[m], a[m]);
#pragma unroll
                for (int n2 = 0; n2 < 4; n2++)
                    FMA2(acc2[m][n2], a2, b2[n2]);
            }
        }
        __syncthreads();
    }

    // Epilogue: unpack, add bias, store
#pragma unroll
    for (int m = 0; m < 8; m++) {
        int r = row0 + ty * 8 + m;
        int c = col0 + tx * 8;
        float4 bv0 = *(const float4*)(bias + c);
        float4 bv1 = *(const float4*)(bias + c + 4);
        float2 u0 = unpack2(acc2[m][0]);
        float2 u1 = unpack2(acc2[m][1]);
        float2 u2 = unpack2(acc2[m][2]);
        float2 u3 = unpack2(acc2[m][3]);
        float4 o0 = make_float4(u0.x + bv0.x, u0.y + bv0.y,
                                u1.x + bv0.z, u1.y + bv0.w);
        float4 o1 = make_float4(u2.x + bv1.x, u2.y + bv1.y,
                                u3.x + bv1.z, u3.y + bv1.w);
        *(float4*)(C + (size_t)r * N + c)     = o0;
        *(float4*)(C + (size_t)r * N + c + 4) = o1;
    }
}

// ============================================================
// Attention: one block per (b,h); one thread per query row p.
// Streams K/V in 64-row chunks through SMEM. Unnormalized
// softmax (logits are |s|<~1 so no max subtraction needed).
// q-row and O accumulator live in registers as f32x2 pairs.
// ============================================================
__global__ __launch_bounds__(256) void attn_kernel(
    const float* __restrict__ q, const float* __restrict__ kmat,
    const float* __restrict__ vmat, float* __restrict__ outm)
{
    __shared__ __align__(16) float ks[64 * 64];
    __shared__ __align__(16) float vs[64 * 64];

    const int b = blockIdx.x >> 4;
    const int h = blockIdx.x & 15;
    const int p = threadIdx.x;

    const float* qp = q + ((size_t)(b * NP + p) * NDM) + h * NDK;
    ull q2[32];
#pragma unroll
    for (int d = 0; d < 64; d += 4) {
        float4 t = *(const float4*)(qp + d);
        q2[d / 2]     = pack2(t.x, t.y);
        q2[d / 2 + 1] = pack2(t.z, t.w);
    }

    ull o2[32];
#pragma unroll
    for (int i = 0; i < 32; i++) o2[i] = 0ull;
    float lsum = 0.0f;

    for (int v0 = 0; v0 < NV; v0 += 64) {
        // Cooperative chunk load: 64x64 K and V slices for this head.
        // SMEM store address = 4*f4 words -> perfectly linear, conflict-free.
#pragma unroll
        for (int i = 0; i < 4; i++) {
            int f4 = p + i * 256;              // 0..1023
            int r  = f4 >> 4;                  // 0..63
            int c4 = f4 & 15;                  // 0..15
            size_t goff = (size_t)(v0 + r) * NDM + h * NDK + c4 * 4;
            ((float4*)ks)[f4] = *(const float4*)(kmat + goff);
            ((float4*)vs)[f4] = *(const float4*)(vmat + goff);
        }
        __syncthreads();

#pragma unroll 2
        for (int j = 0; j < 64; j++) {
            // s = q . k_j  (packed, 2 independent chains)
            const ull* kr = (const ull*)(ks) + j * 32;
            ull s2a = 0ull, s2b = 0ull;
#pragma unroll
            for (int d2 = 0; d2 < 32; d2 += 2) {
                FMA2(s2a, q2[d2],     kr[d2]);
                FMA2(s2b, q2[d2 + 1], kr[d2 + 1]);
            }
            float2 ua = unpack2(s2a), ub = unpack2(s2b);
            float s  = (ua.x + ua.y) + (ub.x + ub.y);
            float pe = __expf(s * (1.0f / 64.0f));
            lsum += pe;
            ull pe2 = pack2(pe, pe);
            const ull* vr = (const ull*)(vs) + j * 32;
#pragma unroll
            for (int d2 = 0; d2 < 32; d2++)
                FMA2(o2[d2], pe2, vr[d2]);
        }
        __syncthreads();
    }

    float inv = 1.0f / lsum;
    float* op = outm + ((size_t)(b * NP + p) * NDM) + h * NDK;
#pragma unroll
    for (int d2 = 0; d2 < 32; d2 += 2) {
        float2 x = unpack2(o2[d2]);
        float2 y = unpack2(o2[d2 + 1]);
        float4 o = make_float4(x.x * inv, x.y * inv, y.x * inv, y.y * inv);
        *(float4*)(op + d2 * 2) = o;
    }
}

// ============================================================
extern "C" void kernel_launch(void* const* d_in, const int* in_sizes, int n_in,
                              void* d_out, int out_size)
{
    const float* query = (const float*)d_in[0];
    const float* key   = (const float*)d_in[1];
    const float* value = (const float*)d_in[2];
    const float* Wq    = (const float*)d_in[3];
    const float* bq    = (const float*)d_in[4];
    const float* Wk    = (const float*)d_in[5];
    const float* bk    = (const float*)d_in[6];
    const float* Wv    = (const float*)d_in[7];
    const float* bv    = (const float*)d_in[8];
    const float* Wo    = (const float*)d_in[9];
    const float* bo    = (const float*)d_in[10];
    float* out = (float*)d_out;

    float *q_, *k_, *v_, *m_;
    cudaGetSymbolAddress((void**)&q_, g_q);
    cudaGetSymbolAddress((void**)&k_, g_k);
    cudaGetSymbolAddress((void**)&v_, g_v);
    cudaGetSymbolAddress((void**)&m_, g_m);

    // q projection: [2048,1024] = query @ Wq + bq
    sgemm_bias<<<dim3(NDM / 128, (NB * NP) / 128), 256>>>(
        query, Wq, bq, q_, NB * NP, NDM, NDM);
    // k projection: [8192,1024] = key @ Wk + bk
    sgemm_bias<<<dim3(NDM / 128, NV / 128), 256>>>(
        key, Wk, bk, k_, NV, NDM, NDL);
    // v projection: [8192,1024] = value @ Wv + bv
    sgemm_bias<<<dim3(NDM / 128, NV / 128), 256>>>(
        value, Wv, bv, v_, NV, NDM, NDL);
    // attention -> mapped [2048,1024]
    attn_kernel<<<NB * NH, 256>>>(q_, k_, v_, m_);
    // output projection: [2048,4096] = mapped @ Wo + bo
    sgemm_bias<<<dim3(NDL / 128, (NB * NP) / 128), 256>>>(
        m_, Wo, bo, out, NB * NP, NDL, NDM);
}

// round 4
// speedup vs baseline: 1.1431x; 1.1431x over previous
#include <cuda_runtime.h>

typedef unsigned long long ull;

#define NB 8
#define NP 256
#define NH 16
#define NDK 64
#define NV 8192
#define NDM 1024
#define NDL 4096

// Scratch (device globals: allocation-free per harness rules)
__device__ float g_q[NB * NP * NDM];   // 8 MB
__device__ float g_k[NV * NDM];        // 32 MB
__device__ float g_v[NV * NDM];        // 32 MB
__device__ float g_m[NB * NP * NDM];   // 8 MB

// ---- packed fp32x2 helpers (Blackwell sm_103a) ----
__device__ __forceinline__ ull pack2(float x, float y) {
    ull r;
    asm("mov.b64 %0, {%1, %2};" : "=l"(r)
        : "r"(__float_as_uint(x)), "r"(__float_as_uint(y)));
    return r;
}
__device__ __forceinline__ float2 unpack2(ull v) {
    unsigned lo, hi;
    asm("mov.b64 {%0, %1}, %2;" : "=r"(lo), "=r"(hi) : "l"(v));
    return make_float2(__uint_as_float(lo), __uint_as_float(hi));
}
#define FMA2(acc, a, b) \
    asm("fma.rn.f32x2 %0, %1, %2, %0;" : "+l"(acc) : "l"(a), "l"(b))

// ============================================================
// SGEMM: C[M,N] = A[M,K] @ B[K,N] + bias[N]
// BM=BN=128, BK=16, 256 threads, 8x8 per-thread tile,
// inner product via packed fma.rn.f32x2 (2 cols per op).
// Requires M%128==0, N%128==0, K%16==0 (true for all calls).
// ============================================================
__global__ __launch_bounds__(256) void sgemm_bias(
    const float* __restrict__ A, const float* __restrict__ Bm,
    const float* __restrict__ bias, float* __restrict__ C,
    int M, int N, int K)
{
    __shared__ __align__(16) float As[16][132];  // transposed A tile, padded
    __shared__ __align__(16) float Bs[16][128];

    const int tid = threadIdx.x;
    const int tx = tid & 15;        // 16 cols of threads -> 8 C-cols each
    const int ty = tid >> 4;        // 16 rows of threads -> 8 C-rows each
    const int row0 = blockIdx.y * 128;
    const int col0 = blockIdx.x * 128;

    ull acc2[8][4];
#pragma unroll
    for (int m = 0; m < 8; m++)
#pragma unroll
        for (int n2 = 0; n2 < 4; n2++) acc2[m][n2] = 0ull;

    for (int k0 = 0; k0 < K; k0 += 16) {
        // Load A tile [128 x 16] -> transposed into As[k][row]
#pragma unroll
        for (int i = 0; i < 2; i++) {
            int f4 = tid + i * 256;            // 0..511
            int r  = f4 >> 2;                  // 0..127
            int kc = (f4 & 3) * 4;             // 0,4,8,12
            float4 av = *(const float4*)(A + (size_t)(row0 + r) * K + k0 + kc);
            As[kc + 0][r] = av.x; As[kc + 1][r] = av.y;
            As[kc + 2][r] = av.z; As[kc + 3][r] = av.w;
        }
        // Load B tile [16 x 128] natural layout
#pragma unroll
        for (int i = 0; i < 2; i++) {
            int f4 = tid + i * 256;
            int kr = f4 >> 5;                  // 0..15
            int c  = (f4 & 31) * 4;            // 0..124
            *(float4*)(&Bs[kr][c]) =
                *(const float4*)(Bm + (size_t)(k0 + kr) * N + col0 + c);
        }
        __syncthreads();

#pragma unroll
        for (int kk = 0; kk < 16; kk++) {
            float4 alo = *(const float4*)(&As[kk][ty * 8]);
            float4 ahi = *(const float4*)(&As[kk][ty * 8 + 4]);
            float a[8] = {alo.x, alo.y, alo.z, alo.w,
                          ahi.x, ahi.y, ahi.z, ahi.w};
            ull b2[4];
#pragma unroll
            for (int n2 = 0; n2 < 4; n2++)
                b2[n2] = *(const ull*)(&Bs[kk][tx * 8 + n2 * 2]);
#pragma unroll
            for (int m = 0; m < 8; m++) {
                ull a2 = pack2(a[m], a[m]);
#pragma unroll
                for (int n2 = 0; n2 < 4; n2++)
                    FMA2(acc2[m][n2], a2, b2[n2]);
            }
        }
        __syncthreads();
    }

    // Epilogue: unpack, add bias, store
#pragma unroll
    for (int m = 0; m < 8; m++) {
        int r = row0 + ty * 8 + m;
        int c = col0 + tx * 8;
        float4 bv0 = *(const float4*)(bias + c);
        float4 bv1 = *(const float4*)(bias + c + 4);
        float2 u0 = unpack2(acc2[m][0]);
        float2 u1 = unpack2(acc2[m][1]);
        float2 u2 = unpack2(acc2[m][2]);
        float2 u3 = unpack2(acc2[m][3]);
        float4 o0 = make_float4(u0.x + bv0.x, u0.y + bv0.y,
                                u1.x + bv0.z, u1.y + bv0.w);
        float4 o1 = make_float4(u2.x + bv1.x, u2.y + bv1.y,
                                u3.x + bv1.z, u3.y + bv1.w);
        *(float4*)(C + (size_t)r * N + c)     = o0;
        *(float4*)(C + (size_t)r * N + c + 4) = o1;
    }
}

// ============================================================
// Attention: one block per (b,h); one thread per query row p.
// Streams K/V in 64-row chunks through SMEM. Unnormalized
// softmax (logits are |s|<~1 so no max subtraction needed).
// q-row and O accumulator live in registers as f32x2 pairs.
// ============================================================
__global__ __launch_bounds__(256) void attn_kernel(
    const float* __restrict__ q, const float* __restrict__ kmat,
    const float* __restrict__ vmat, float* __restrict__ outm)
{
    __shared__ __align__(16) float ks[64 * 64];
    __shared__ __align__(16) float vs[64 * 64];

    const int b = blockIdx.x >> 4;
    const int h = blockIdx.x & 15;
    const int p = threadIdx.x;

    const float* qp = q + ((size_t)(b * NP + p) * NDM) + h * NDK;
    ull q2[32];
#pragma unroll
    for (int d = 0; d < 64; d += 4) {
        float4 t = *(const float4*)(qp + d);
        q2[d / 2]     = pack2(t.x, t.y);
        q2[d / 2 + 1] = pack2(t.z, t.w);
    }

    ull o2[32];
#pragma unroll
    for (int i = 0; i < 32; i++) o2[i] = 0ull;
    float lsum = 0.0f;

    for (int v0 = 0; v0 < NV; v0 += 64) {
        // Cooperative chunk load: 64x64 K and V slices for this head.
        // SMEM store address = 4*f4 words -> perfectly linear, conflict-free.
#pragma unroll
        for (int i = 0; i < 4; i++) {
            int f4 = p + i * 256;              // 0..1023
            int r  = f4 >> 4;                  // 0..63
            int c4 = f4 & 15;                  // 0..15
            size_t goff = (size_t)(v0 + r) * NDM + h * NDK + c4 * 4;
            ((float4*)ks)[f4] = *(const float4*)(kmat + goff);
            ((float4*)vs)[f4] = *(const float4*)(vmat + goff);
        }
        __syncthreads();

#pragma unroll 2
        for (int j = 0; j < 64; j++) {
            // s = q . k_j  (packed, 2 independent chains)
            const ull* kr = (const ull*)(ks) + j * 32;
            ull s2a = 0ull, s2b = 0ull;
#pragma unroll
            for (int d2 = 0; d2 < 32; d2 += 2) {
                FMA2(s2a, q2[d2],     kr[d2]);
                FMA2(s2b, q2[d2 + 1], kr[d2 + 1]);
            }
            float2 ua = unpack2(s2a), ub = unpack2(s2b);
            float s  = (ua.x + ua.y) + (ub.x + ub.y);
            float pe = __expf(s * (1.0f / 64.0f));
            lsum += pe;
            ull pe2 = pack2(pe, pe);
            const ull* vr = (const ull*)(vs) + j * 32;
#pragma unroll
            for (int d2 = 0; d2 < 32; d2++)
                FMA2(o2[d2], pe2, vr[d2]);
        }
        __syncthreads();
    }

    float inv = 1.0f / lsum;
    float* op = outm + ((size_t)(b * NP + p) * NDM) + h * NDK;
#pragma unroll
    for (int d2 = 0; d2 < 32; d2 += 2) {
        float2 x = unpack2(o2[d2]);
        float2 y = unpack2(o2[d2 + 1]);
        float4 o = make_float4(x.x * inv, x.y * inv, y.x * inv, y.y * inv);
        *(float4*)(op + d2 * 2) = o;
    }
}

// ============================================================
extern "C" void kernel_launch(void* const* d_in, const int* in_sizes, int n_in,
                              void* d_out, int out_size)
{
    const float* query = (const float*)d_in[0];
    const float* key   = (const float*)d_in[1];
    const float* value = (const float*)d_in[2];
    const float* Wq    = (const float*)d_in[3];
    const float* bq    = (const float*)d_in[4];
    const float* Wk    = (const float*)d_in[5];
    const float* bk    = (const float*)d_in[6];
    const float* Wv    = (const float*)d_in[7];
    const float* bv    = (const float*)d_in[8];
    const float* Wo    = (const float*)d_in[9];
    const float* bo    = (const float*)d_in[10];
    float* out = (float*)d_out;

    float *q_, *k_, *v_, *m_;
    cudaGetSymbolAddress((void**)&q_, g_q);
    cudaGetSymbolAddress((void**)&k_, g_k);
    cudaGetSymbolAddress((void**)&v_, g_v);
    cudaGetSymbolAddress((void**)&m_, g_m);

    // q projection: [2048,1024] = query @ Wq + bq
    sgemm_bias<<<dim3(NDM / 128, (NB * NP) / 128), 256>>>(
        query, Wq, bq, q_, NB * NP, NDM, NDM);
    // k projection: [8192,1024] = key @ Wk + bk
    sgemm_bias<<<dim3(NDM / 128, NV / 128), 256>>>(
        key, Wk, bk, k_, NV, NDM, NDL);
    // v projection: [8192,1024] = value @ Wv + bv
    sgemm_bias<<<dim3(NDM / 128, NV / 128), 256>>>(
        value, Wv, bv, v_, NV, NDM, NDL);
    // attention -> mapped [2048,1024]
    attn_kernel<<<NB * NH, 256>>>(q_, k_, v_, m_);
    // output projection: [2048,4096] = mapped @ Wo + bo
    sgemm_bias<<<dim3(NDL / 128, (NB * NP) / 128), 256>>>(
        m_, Wo, bo, out, NB * NP, NDL, NDM);
}

// round 6
// speedup vs baseline: 1.6102x; 1.4086x over previous
#include <cuda_runtime.h>
#include <cuda_bf16.h>
#include <cstdint>

typedef unsigned long long ull;

#define NB 8
#define NP 256
#define NH 16
#define NDK 64
#define NV 8192
#define NDM 1024
#define NDL 4096
#define NQ (NB*NP)

// ---------------- device scratch (allocation-free per harness rules) ----------------
__device__ float g_q[(size_t)NQ * NDM];
__device__ float g_k[(size_t)NV * NDM];
__device__ float g_v[(size_t)NV * NDM];
__device__ float g_m[(size_t)NQ * NDM];
__device__ float g_part[2 * (size_t)NQ * NDM];   // V-split attention partials
__device__ float g_lsum[2 * (size_t)NQ * NH];    // V-split exp-sums

__device__ __nv_bfloat16 g_qryh[(size_t)NQ * NDM], g_qryl[(size_t)NQ * NDM];
__device__ __nv_bfloat16 g_keyh[(size_t)NV * NDL], g_keyl[(size_t)NV * NDL];
__device__ __nv_bfloat16 g_valh[(size_t)NV * NDL], g_vall[(size_t)NV * NDL];
__device__ __nv_bfloat16 g_maph[(size_t)NQ * NDM], g_mapl[(size_t)NQ * NDM];
__device__ __nv_bfloat16 g_Wqh[(size_t)NDM * NDM], g_Wql[(size_t)NDM * NDM]; // Wq^T [1024,1024]
__device__ __nv_bfloat16 g_Wkh[(size_t)NDM * NDL], g_Wkl[(size_t)NDM * NDL]; // Wk^T [1024,4096]
__device__ __nv_bfloat16 g_Wvh[(size_t)NDM * NDL], g_Wvl[(size_t)NDM * NDL]; // Wv^T [1024,4096]
__device__ __nv_bfloat16 g_Woh[(size_t)NDL * NDM], g_Wol[(size_t)NDL * NDM]; // Wo^T [4096,1024]

// ---------------- helpers ----------------
__device__ __forceinline__ uint32_t smem_u32(const void* p) {
    uint32_t a;
    asm("{ .reg .u64 t; cvta.to.shared.u64 t, %1; cvt.u32.u64 %0, t; }" : "=r"(a) : "l"(p));
    return a;
}
#define SW128(off) ((uint32_t)(off) ^ (((uint32_t)(off) >> 3) & 0x70))

__device__ __forceinline__ void cp16(uint32_t so, const void* g) {
    asm volatile("cp.async.cg.shared.global [%0], [%1], 16;" :: "r"(so), "l"(g));
}
#define CP_COMMIT() asm volatile("cp.async.commit_group;" ::: "memory")
#define CP_WAIT(n)  asm volatile("cp.async.wait_group %0;" :: "n"(n) : "memory")

#define LDSM4(r, addr) \
    asm volatile("ldmatrix.sync.aligned.m8n8.x4.shared.b16 {%0,%1,%2,%3}, [%4];" \
        : "=r"((r)[0]), "=r"((r)[1]), "=r"((r)[2]), "=r"((r)[3]) : "r"(addr))

#define MMA16816(d, a, b0, b1) \
    asm volatile("mma.sync.aligned.m16n8k16.row.col.f32.bf16.bf16.f32 " \
        "{%0,%1,%2,%3}, {%4,%5,%6,%7}, {%8,%9}, {%0,%1,%2,%3};" \
        : "+f"((d)[0]), "+f"((d)[1]), "+f"((d)[2]), "+f"((d)[3]) \
        : "r"((a)[0]), "r"((a)[1]), "r"((a)[2]), "r"((a)[3]), "r"(b0), "r"(b1))

// ---- packed fp32x2 ----
__device__ __forceinline__ ull pack2(float x, float y) {
    ull r;
    asm("mov.b64 %0, {%1, %2};" : "=l"(r) : "r"(__float_as_uint(x)), "r"(__float_as_uint(y)));
    return r;
}
__device__ __forceinline__ float2 unpack2(ull v) {
    unsigned lo, hi;
    asm("mov.b64 {%0, %1}, %2;" : "=r"(lo), "=r"(hi) : "l"(v));
    return make_float2(__uint_as_float(lo), __uint_as_float(hi));
}
#define FMA2(acc, a, b) asm("fma.rn.f32x2 %0, %1, %2, %0;" : "+l"(acc) : "l"(a), "l"(b))

// ============================================================
// bf16x3-split HMMA GEMM: C[M,N] = A@W + bias
// A hi/lo: [M,K] K-major bf16;  B hi/lo: W^T as [N,K] K-major bf16.
// BM=BN=128, BK=64; 256 thr (8 warps 4x2, warp tile 32x64);
// SW128 smem; 2-stage cp.async; mma.sync m16n8k16 fp32 accum.
// ============================================================
#define TILEB 16384
#define STAGEB 32768
#define GSMEM (2*STAGEB)

__device__ __forceinline__ void load_tile_h(
    uint32_t st, const __nv_bfloat16* __restrict__ A,
    const __nv_bfloat16* __restrict__ B, int m0, int n0, int K, int k0, int tid)
{
    const __nv_bfloat16* pa = A + (size_t)m0 * K + k0;
    const __nv_bfloat16* pb = B + (size_t)n0 * K + k0;
#pragma unroll
    for (int i = 0; i < 4; i++) {
        int c = tid + (i << 8);                 // 0..1023 16B-chunks
        int r = c >> 3, j = c & 7;              // row 0..127, chunk 0..7
        uint32_t so = SW128((r << 7) + (j << 4));
        cp16(st + so,         pa + (size_t)r * K + (j << 3));
        cp16(st + TILEB + so, pb + (size_t)r * K + (j << 3));
    }
    CP_COMMIT();
}

__global__ __launch_bounds__(256) void gemm_hmma(
    const __nv_bfloat16* __restrict__ Ah, const __nv_bfloat16* __restrict__ Al,
    const __nv_bfloat16* __restrict__ Bh, const __nv_bfloat16* __restrict__ Bl,
    const float* __restrict__ bias, float* __restrict__ C,
    int M, int N, int K)
{
    extern __shared__ __align__(128) char smraw[];
    uint32_t sb = smem_u32(smraw);
    const int tid = threadIdx.x, lane = tid & 31, wid = tid >> 5;
    const int wm = wid & 3, wn = wid >> 2;             // 4 x 2 warp grid
    const int m0 = blockIdx.y * 128, n0 = blockIdx.x * 128;

    float acc[2][8][4];
#pragma unroll
    for (int i = 0; i < 2; i++)
#pragma unroll
        for (int j = 0; j < 8; j++)
#pragma unroll
            for (int c = 0; c < 4; c++) acc[i][j][c] = 0.0f;

    const int kT = K >> 6;
    const int nIter = 3 * kT;

    load_tile_h(sb, Ah, Bh, m0, n0, K, 0, tid);

    // per-lane ldmatrix row/chunk offsets (constant across iterations)
    const int arow = wm * 32 + (lane & 7) + ((lane & 8) ? 8 : 0);
    const int akoff = (lane & 16) ? 16 : 0;
    const int brow = wn * 64 + (lane & 7) + ((lane & 16) ? 8 : 0);
    const int bkoff = (lane & 8) ? 16 : 0;

    for (int it = 0; it < nIter; it++) {
        int buf = it & 1;
        if (it + 1 < nIter) {
            int nit = it + 1;
            int pass = nit / kT, kt = nit - pass * kT;
            const __nv_bfloat16* Ap = (pass == 1) ? Al : Ah;
            const __nv_bfloat16* Bp = (pass == 2) ? Bl : Bh;
            load_tile_h(sb + (buf ^ 1) * STAGEB, Ap, Bp, m0, n0, K, kt << 6, tid);
            CP_WAIT(1);
        } else {
            CP_WAIT(0);
        }
        __syncthreads();

        uint32_t abase = sb + buf * STAGEB;
        uint32_t bbase = abase + TILEB;
#pragma unroll
        for (int ks = 0; ks < 4; ks++) {
            int kb = ks * 32;  // bytes into the 128B row
            uint32_t af[2][4];
#pragma unroll
            for (int i = 0; i < 2; i++)
                LDSM4(af[i], abase + SW128((arow + i * 16) * 128 + kb + akoff));
            uint32_t bfg[4][4];
#pragma unroll
            for (int j = 0; j < 4; j++)
                LDSM4(bfg[j], bbase + SW128((brow + j * 16) * 128 + kb + bkoff));
#pragma unroll
            for (int i = 0; i < 2; i++)
#pragma unroll
                for (int j = 0; j < 4; j++) {
                    MMA16816(acc[i][2 * j],     af[i], bfg[j][0], bfg[j][1]);
                    MMA16816(acc[i][2 * j + 1], af[i], bfg[j][2], bfg[j][3]);
                }
        }
        __syncthreads();
    }

    // epilogue: direct stores, bias add
#pragma unroll
    for (int i = 0; i < 2; i++) {
        int row = m0 + wm * 32 + i * 16 + (lane >> 2);
#pragma unroll
        for (int j = 0; j < 8; j++) {
            int col = n0 + wn * 64 + j * 8 + (lane & 3) * 2;
            float2 bv = *(const float2*)(bias + col);
            float2 v0 = make_float2(acc[i][j][0] + bv.x, acc[i][j][1] + bv.y);
            float2 v1 = make_float2(acc[i][j][2] + bv.x, acc[i][j][3] + bv.y);
            *(float2*)(C + (size_t)row * N + col)       = v0;
            *(float2*)(C + (size_t)(row + 8) * N + col) = v1;
        }
    }
}

// ============================================================
// fp32 -> (bf16 hi, bf16 lo) elementwise split
// ============================================================
__global__ __launch_bounds__(256) void split4(
    const float* __restrict__ x, __nv_bfloat162* __restrict__ h,
    __nv_bfloat162* __restrict__ l, int n4)
{
    int i = blockIdx.x * blockDim.x + threadIdx.x;
    if (i >= n4) return;
    float4 v = ((const float4*)x)[i];
    __nv_bfloat16 h0 = __float2bfloat16(v.x), h1 = __float2bfloat16(v.y);
    __nv_bfloat16 h2 = __float2bfloat16(v.z), h3 = __float2bfloat16(v.w);
    h[2 * i]     = __halves2bfloat162(h0, h1);
    h[2 * i + 1] = __halves2bfloat162(h2, h3);
    l[2 * i]     = __halves2bfloat162(__float2bfloat16(v.x - __bfloat162float(h0)),
                                      __float2bfloat16(v.y - __bfloat162float(h1)));
    l[2 * i + 1] = __halves2bfloat162(__float2bfloat16(v.z - __bfloat162float(h2)),
                                      __float2bfloat16(v.w - __bfloat162float(h3)));
}

// ============================================================
// W [K,N] fp32 -> W^T [N,K] bf16 hi/lo (tiled transpose)
// ============================================================
__global__ void transpose_split(const float* __restrict__ W,
                                __nv_bfloat16* __restrict__ Th,
                                __nv_bfloat16* __restrict__ Tl, int K, int N)
{
    __shared__ float t[32][33];
    int n = blockIdx.x * 32 + threadIdx.x;
    int k = blockIdx.y * 32 + threadIdx.y;
    t[threadIdx.y][threadIdx.x] = W[(size_t)k * N + n];
    __syncthreads();
    int kk = blockIdx.y * 32 + threadIdx.x;
    int nn = blockIdx.x * 32 + threadIdx.y;
    float v = t[threadIdx.x][threadIdx.y];
    __nv_bfloat16 hv = __float2bfloat16(v);
    Th[(size_t)nn * K + kk] = hv;
    Tl[(size_t)nn * K + kk] = __float2bfloat16(v - __bfloat162float(hv));
}

// ============================================================
// Attention (fp32x2), V-split x2, row-split x2:
// grid 512 blocks of 128 threads; block idx = (((b*16+h)*2+rh)*2+vs).
// Unnormalized softmax partials written to g_part/g_lsum.
// ============================================================
__global__ __launch_bounds__(128) void attn2(
    const float* __restrict__ q, const float* __restrict__ kmat,
    const float* __restrict__ vmat, float* __restrict__ part,
    float* __restrict__ lsums)
{
    __shared__ __align__(16) float ks[64 * 64];
    __shared__ __align__(16) float vs[64 * 64];

    const int idx = blockIdx.x;
    const int vsp = idx & 1;
    const int rh  = (idx >> 1) & 1;
    const int h   = (idx >> 2) & 15;
    const int b   = idx >> 6;
    const int p   = rh * 128 + threadIdx.x;
    const int tid = threadIdx.x;

    const float* qp = q + ((size_t)(b * NP + p) * NDM) + h * NDK;
    ull q2[32];
#pragma unroll
    for (int d = 0; d < 64; d += 4) {
        float4 t = *(const float4*)(qp + d);
        q2[d / 2]     = pack2(t.x, t.y);
        q2[d / 2 + 1] = pack2(t.z, t.w);
    }

    ull o2[32];
#pragma unroll
    for (int i = 0; i < 32; i++) o2[i] = 0ull;
    float lsum = 0.0f;

    const int vbeg = vsp * (NV / 2), vend = vbeg + NV / 2;
    for (int v0 = vbeg; v0 < vend; v0 += 64) {
#pragma unroll
        for (int i = 0; i < 8; i++) {
            int f4 = tid + i * 128;            // 0..1023
            int r  = f4 >> 4;
            int c4 = f4 & 15;
            size_t goff = (size_t)(v0 + r) * NDM + h * NDK + c4 * 4;
            ((float4*)ks)[f4] = *(const float4*)(kmat + goff);
            ((float4*)vs)[f4] = *(const float4*)(vmat + goff);
        }
        __syncthreads();

#pragma unroll 2
        for (int j = 0; j < 64; j++) {
            const ull* kr = (const ull*)(ks) + j * 32;
            ull s2a = 0ull, s2b = 0ull, s2c = 0ull, s2d = 0ull;
#pragma unroll
            for (int d2 = 0; d2 < 32; d2 += 4) {
                FMA2(s2a, q2[d2],     kr[d2]);
                FMA2(s2b, q2[d2 + 1], kr[d2 + 1]);
                FMA2(s2c, q2[d2 + 2], kr[d2 + 2]);
                FMA2(s2d, q2[d2 + 3], kr[d2 + 3]);
            }
            float2 ua = unpack2(s2a), ub = unpack2(s2b);
            float2 uc = unpack2(s2c), ud = unpack2(s2d);
            float s  = ((ua.x + ua.y) + (ub.x + ub.y)) +
                       ((uc.x + uc.y) + (ud.x + ud.y));
            float pe = __expf(s * (1.0f / 64.0f));
            lsum += pe;
            ull pe2 = pack2(pe, pe);
            const ull* vr = (const ull*)(vs) + j * 32;
#pragma unroll
            for (int d2 = 0; d2 < 32; d2++)
                FMA2(o2[d2], pe2, vr[d2]);
        }
        __syncthreads();
    }

    float* op = part + (size_t)vsp * NQ * NDM + ((size_t)(b * NP + p) * NDM) + h * NDK;
#pragma unroll
    for (int d2 = 0; d2 < 32; d2 += 2) {
        float2 x = unpack2(o2[d2]);
        float2 y = unpack2(o2[d2 + 1]);
        *(float4*)(op + d2 * 2) = make_float4(x.x, x.y, y.x, y.y);
    }
    lsums[(size_t)vsp * NQ * NH + (size_t)(b * NP + p) * NH + h] = lsum;
}

// combine the two V-split partials: out = (pA + pB) / (lA + lB)
__global__ __launch_bounds__(256) void attn_combine(
    const float* __restrict__ part, const float* __restrict__ lsums,
    float* __restrict__ outm)
{
    int i = blockIdx.x * blockDim.x + threadIdx.x;    // float4 index
    if (i >= NQ * NDM / 4) return;
    int row = i >> 8;             // 256 float4 per row
    int h = (i & 255) >> 4;       // 16 float4 per head block
    float l = lsums[(size_t)row * NH + h] +
              lsums[(size_t)NQ * NH + (size_t)row * NH + h];
    float inv = 1.0f / l;
    float4 a = ((const float4*)part)[i];
    float4 b = ((const float4*)part)[(size_t)NQ * NDM / 4 + i];
    ((float4*)outm)[i] = make_float4((a.x + b.x) * inv, (a.y + b.y) * inv,
                                     (a.z + b.z) * inv, (a.w + b.w) * inv);
}

// ============================================================
extern "C" void kernel_launch(void* const* d_in, const int* in_sizes, int n_in,
                              void* d_out, int out_size)
{
    const float* query = (const float*)d_in[0];
    const float* key   = (const float*)d_in[1];
    const float* value = (const float*)d_in[2];
    const float* Wq    = (const float*)d_in[3];
    const float* bq    = (const float*)d_in[4];
    const float* Wk    = (const float*)d_in[5];
    const float* bk    = (const float*)d_in[6];
    const float* Wv    = (const float*)d_in[7];
    const float* bv    = (const float*)d_in[8];
    const float* Wo    = (const float*)d_in[9];
    const float* bo    = (const float*)d_in[10];
    float* out = (float*)d_out;

    float *q_, *k_, *v_, *m_, *part_, *ls_;
    cudaGetSymbolAddress((void**)&q_, g_q);
    cudaGetSymbolAddress((void**)&k_, g_k);
    cudaGetSymbolAddress((void**)&v_, g_v);
    cudaGetSymbolAddress((void**)&m_, g_m);
    cudaGetSymbolAddress((void**)&part_, g_part);
    cudaGetSymbolAddress((void**)&ls_, g_lsum);

    __nv_bfloat16 *qh, *ql, *kh, *kl, *vh, *vl, *mh, *ml;
    __nv_bfloat16 *wqh, *wql, *wkh, *wkl, *wvh, *wvl, *woh, *wol;
    cudaGetSymbolAddress((void**)&qh, g_qryh);  cudaGetSymbolAddress((void**)&ql, g_qryl);
    cudaGetSymbolAddress((void**)&kh, g_keyh);  cudaGetSymbolAddress((void**)&kl, g_keyl);
    cudaGetSymbolAddress((void**)&vh, g_valh);  cudaGetSymbolAddress((void**)&vl, g_vall);
    cudaGetSymbolAddress((void**)&mh, g_maph);  cudaGetSymbolAddress((void**)&ml, g_mapl);
    cudaGetSymbolAddress((void**)&wqh, g_Wqh);  cudaGetSymbolAddress((void**)&wql, g_Wql);
    cudaGetSymbolAddress((void**)&wkh, g_Wkh);  cudaGetSymbolAddress((void**)&wkl, g_Wkl);
    cudaGetSymbolAddress((void**)&wvh, g_Wvh);  cudaGetSymbolAddress((void**)&wvl, g_Wvl);
    cudaGetSymbolAddress((void**)&woh, g_Woh);  cudaGetSymbolAddress((void**)&wol, g_Wol);

    cudaFuncSetAttribute(gemm_hmma, cudaFuncAttributeMaxDynamicSharedMemorySize, GSMEM);

    // --- operand prep: weight transposes + activation splits ---
    transpose_split<<<dim3(NDM / 32, NDM / 32), dim3(32, 32)>>>(Wq, wqh, wql, NDM, NDM);
    transpose_split<<<dim3(NDM / 32, NDL / 32), dim3(32, 32)>>>(Wk, wkh, wkl, NDL, NDM);
    transpose_split<<<dim3(NDM / 32, NDL / 32), dim3(32, 32)>>>(Wv, wvh, wvl, NDL, NDM);
    transpose_split<<<dim3(NDL / 32, NDM / 32), dim3(32, 32)>>>(Wo, woh, wol, NDM, NDL);
    {
        int n4 = NQ * NDM / 4;
        split4<<<(n4 + 255) / 256, 256>>>(query, (__nv_bfloat162*)qh, (__nv_bfloat162*)ql, n4);
    }
    {
        int n4 = NV * NDL / 4;
        split4<<<(n4 + 255) / 256, 256>>>(key,   (__nv_bfloat162*)kh, (__nv_bfloat162*)kl, n4);
        split4<<<(n4 + 255) / 256, 256>>>(value, (__nv_bfloat162*)vh, (__nv_bfloat162*)vl, n4);
    }

    // --- projections on HMMA tensor cores ---
    gemm_hmma<<<dim3(NDM / 128, NQ / 128), 256, GSMEM>>>(qh, ql, wqh, wql, bq, q_, NQ, NDM, NDM);
    gemm_hmma<<<dim3(NDM / 128, NV / 128), 256, GSMEM>>>(kh, kl, wkh, wkl, bk, k_, NV, NDM, NDL);
    gemm_hmma<<<dim3(NDM / 128, NV / 128), 256, GSMEM>>>(vh, vl, wvh, wvl, bv, v_, NV, NDM, NDL);

    // --- attention (V-split x2) ---
    attn2<<<NB * NH * 4, 128>>>(q_, k_, v_, part_, ls_);
    {
        int n4 = NQ * NDM / 4;
        attn_combine<<<(n4 + 255) / 256, 256>>>(part_, ls_, m_);
    }

    // --- output projection ---
    {
        int n4 = NQ * NDM / 4;
        split4<<<(n4 + 255) / 256, 256>>>(m_, (__nv_bfloat162*)mh, (__nv_bfloat162*)ml, n4);
    }
    gemm_hmma<<<dim3(NDL / 128, NQ / 128), 256, GSMEM>>>(mh, ml, woh, wol, bo, out, NQ, NDL, NDM);
}

// round 8
// speedup vs baseline: 1.8127x; 1.1258x over previous
#include <cuda_runtime.h>
#include <cuda_bf16.h>
#include <cstdint>

typedef unsigned long long ull;

#define NB 8
#define NP 256
#define NH 16
#define NDK 64
#define NV 8192
#define NDM 1024
#define NDL 4096
#define NQ (NB*NP)

// ---------------- device scratch (allocation-free per harness rules) ----------------
__device__ float g_q[(size_t)NQ * NDM];
__device__ float g_k[(size_t)NV * NDM];
__device__ float g_v[(size_t)NV * NDM];
__device__ float g_part[2 * (size_t)NQ * NDM];   // V-split attention partials
__device__ float g_lsum[2 * (size_t)NQ * NH];    // V-split exp-sums

__device__ __nv_bfloat16 g_qryh[(size_t)NQ * NDM], g_qryl[(size_t)NQ * NDM];
__device__ __nv_bfloat16 g_keyh[(size_t)NV * NDL], g_keyl[(size_t)NV * NDL];
__device__ __nv_bfloat16 g_valh[(size_t)NV * NDL], g_vall[(size_t)NV * NDL];
__device__ __nv_bfloat16 g_maph[(size_t)NQ * NDM], g_mapl[(size_t)NQ * NDM];
__device__ __nv_bfloat16 g_Wqh[(size_t)NDM * NDM], g_Wql[(size_t)NDM * NDM]; // Wq^T [1024,1024]
__device__ __nv_bfloat16 g_Wkh[(size_t)NDM * NDL], g_Wkl[(size_t)NDM * NDL]; // Wk^T [1024,4096]
__device__ __nv_bfloat16 g_Wvh[(size_t)NDM * NDL], g_Wvl[(size_t)NDM * NDL]; // Wv^T [1024,4096]
__device__ __nv_bfloat16 g_Woh[(size_t)NDL * NDM], g_Wol[(size_t)NDL * NDM]; // Wo^T [4096,1024]

// ---------------- helpers ----------------
__device__ __forceinline__ uint32_t smem_u32(const void* p) {
    uint32_t a;
    asm("{ .reg .u64 t; cvta.to.shared.u64 t, %1; cvt.u32.u64 %0, t; }" : "=r"(a) : "l"(p));
    return a;
}
#define SW128(off) ((uint32_t)(off) ^ (((uint32_t)(off) >> 3) & 0x70))

__device__ __forceinline__ void cp16(uint32_t so, const void* g) {
    asm volatile("cp.async.cg.shared.global [%0], [%1], 16;" :: "r"(so), "l"(g));
}
#define CP_COMMIT() asm volatile("cp.async.commit_group;" ::: "memory")
#define CP_WAIT(n)  asm volatile("cp.async.wait_group %0;" :: "n"(n) : "memory")

#define LDSM4(r, addr) \
    asm volatile("ldmatrix.sync.aligned.m8n8.x4.shared.b16 {%0,%1,%2,%3}, [%4];" \
        : "=r"((r)[0]), "=r"((r)[1]), "=r"((r)[2]), "=r"((r)[3]) : "r"(addr))

#define MMA16816(d, a, b0, b1) \
    asm volatile("mma.sync.aligned.m16n8k16.row.col.f32.bf16.bf16.f32 " \
        "{%0,%1,%2,%3}, {%4,%5,%6,%7}, {%8,%9}, {%0,%1,%2,%3};" \
        : "+f"((d)[0]), "+f"((d)[1]), "+f"((d)[2]), "+f"((d)[3]) \
        : "r"((a)[0]), "r"((a)[1]), "r"((a)[2]), "r"((a)[3]), "r"(b0), "r"(b1))

// ---- packed fp32x2 ----
__device__ __forceinline__ ull pack2(float x, float y) {
    ull r;
    asm("mov.b64 %0, {%1, %2};" : "=l"(r) : "r"(__float_as_uint(x)), "r"(__float_as_uint(y)));
    return r;
}
__device__ __forceinline__ float2 unpack2(ull v) {
    unsigned lo, hi;
    asm("mov.b64 {%0, %1}, %2;" : "=r"(lo), "=r"(hi) : "l"(v));
    return make_float2(__uint_as_float(lo), __uint_as_float(hi));
}
#define FMA2(acc, a, b) asm("fma.rn.f32x2 %0, %1, %2, %0;" : "+l"(acc) : "l"(a), "l"(b))

// ============================================================
// bf16 split HMMA GEMM: C[M,N] = A@W + bias, nPass in {1,3}
//  pass0: Ah*Bh   pass1: Al*Bh   pass2: Ah*Bl
// A hi/lo: [M,K] K-major bf16;  B hi/lo: W^T as [N,K] K-major bf16.
// BM=BN=128, BK=64; 256 thr (8 warps 4x2, warp tile 32x64);
// SW128 smem; 2-stage cp.async; mma.sync m16n8k16 fp32 accum.
// ============================================================
#define TILEB 16384
#define STAGEB 32768
#define GSMEM (2*STAGEB)

__device__ __forceinline__ void load_tile_h(
    uint32_t st, const __nv_bfloat16* __restrict__ A,
    const __nv_bfloat16* __restrict__ B, int m0, int n0, int K, int k0, int tid)
{
    const __nv_bfloat16* pa = A + (size_t)m0 * K + k0;
    const __nv_bfloat16* pb = B + (size_t)n0 * K + k0;
#pragma unroll
    for (int i = 0; i < 4; i++) {
        int c = tid + (i << 8);                 // 0..1023 16B-chunks
        int r = c >> 3, j = c & 7;              // row 0..127, chunk 0..7
        uint32_t so = SW128((r << 7) + (j << 4));
        cp16(st + so,         pa + (size_t)r * K + (j << 3));
        cp16(st + TILEB + so, pb + (size_t)r * K + (j << 3));
    }
    CP_COMMIT();
}

__global__ __launch_bounds__(256) void gemm_hmma(
    const __nv_bfloat16* __restrict__ Ah, const __nv_bfloat16* __restrict__ Al,
    const __nv_bfloat16* __restrict__ Bh, const __nv_bfloat16* __restrict__ Bl,
    const float* __restrict__ bias, float* __restrict__ C,
    int M, int N, int K, int nPass)
{
    extern __shared__ __align__(128) char smraw[];
    uint32_t sb = smem_u32(smraw);
    const int tid = threadIdx.x, lane = tid & 31, wid = tid >> 5;
    const int wm = wid & 3, wn = wid >> 2;             // 4 x 2 warp grid
    const int m0 = blockIdx.y * 128, n0 = blockIdx.x * 128;

    float acc[2][8][4];
#pragma unroll
    for (int i = 0; i < 2; i++)
#pragma unroll
        for (int j = 0; j < 8; j++)
#pragma unroll
            for (int c = 0; c < 4; c++) acc[i][j][c] = 0.0f;

    const int kT = K >> 6;
    const int nIter = nPass * kT;

    load_tile_h(sb, Ah, Bh, m0, n0, K, 0, tid);

    // per-lane ldmatrix row/chunk offsets (constant across iterations)
    const int arow = wm * 32 + (lane & 7) + ((lane & 8) ? 8 : 0);
    const int akoff = (lane & 16) ? 16 : 0;
    const int brow = wn * 64 + (lane & 7) + ((lane & 16) ? 8 : 0);
    const int bkoff = (lane & 8) ? 16 : 0;

    for (int it = 0; it < nIter; it++) {
        int buf = it & 1;
        if (it + 1 < nIter) {
            int nit = it + 1;
            int pass = nit / kT, kt = nit - pass * kT;
            const __nv_bfloat16* Ap = (pass == 1) ? Al : Ah;
            const __nv_bfloat16* Bp = (pass == 2) ? Bl : Bh;
            load_tile_h(sb + (buf ^ 1) * STAGEB, Ap, Bp, m0, n0, K, kt << 6, tid);
            CP_WAIT(1);
        } else {
            CP_WAIT(0);
        }
        __syncthreads();

        uint32_t abase = sb + buf * STAGEB;
        uint32_t bbase = abase + TILEB;
#pragma unroll
        for (int ks = 0; ks < 4; ks++) {
            int kb = ks * 32;  // bytes into the 128B row
            uint32_t af[2][4];
#pragma unroll
            for (int i = 0; i < 2; i++)
                LDSM4(af[i], abase + SW128((arow + i * 16) * 128 + kb + akoff));
            uint32_t bfg[4][4];
#pragma unroll
            for (int j = 0; j < 4; j++)
                LDSM4(bfg[j], bbase + SW128((brow + j * 16) * 128 + kb + bkoff));
#pragma unroll
            for (int i = 0; i < 2; i++)
#pragma unroll
                for (int j = 0; j < 4; j++) {
                    MMA16816(acc[i][2 * j],     af[i], bfg[j][0], bfg[j][1]);
                    MMA16816(acc[i][2 * j + 1], af[i], bfg[j][2], bfg[j][3]);
                }
        }
        __syncthreads();
    }

    // epilogue: direct stores, bias add
#pragma unroll
    for (int i = 0; i < 2; i++) {
        int row = m0 + wm * 32 + i * 16 + (lane >> 2);
#pragma unroll
        for (int j = 0; j < 8; j++) {
            int col = n0 + wn * 64 + j * 8 + (lane & 3) * 2;
            float2 bv = *(const float2*)(bias + col);
            float2 v0 = make_float2(acc[i][j][0] + bv.x, acc[i][j][1] + bv.y);
            float2 v1 = make_float2(acc[i][j][2] + bv.x, acc[i][j][3] + bv.y);
            *(float2*)(C + (size_t)row * N + col)       = v0;
            *(float2*)(C + (size_t)(row + 8) * N + col) = v1;
        }
    }
}

// ============================================================
// fp32 -> (bf16 hi, bf16 lo) elementwise split
// ============================================================
__global__ __launch_bounds__(256) void split4(
    const float* __restrict__ x, __nv_bfloat162* __restrict__ h,
    __nv_bfloat162* __restrict__ l, int n4)
{
    int i = blockIdx.x * blockDim.x + threadIdx.x;
    if (i >= n4) return;
    float4 v = ((const float4*)x)[i];
    __nv_bfloat16 h0 = __float2bfloat16(v.x), h1 = __float2bfloat16(v.y);
    __nv_bfloat16 h2 = __float2bfloat16(v.z), h3 = __float2bfloat16(v.w);
    h[2 * i]     = __halves2bfloat162(h0, h1);
    h[2 * i + 1] = __halves2bfloat162(h2, h3);
    l[2 * i]     = __halves2bfloat162(__float2bfloat16(v.x - __bfloat162float(h0)),
                                      __float2bfloat16(v.y - __bfloat162float(h1)));
    l[2 * i + 1] = __halves2bfloat162(__float2bfloat16(v.z - __bfloat162float(h2)),
                                      __float2bfloat16(v.w - __bfloat162float(h3)));
}

// ============================================================
// W [K,N] fp32 -> W^T [N,K] bf16 hi/lo (tiled transpose)
// ============================================================
__global__ void transpose_split(const float* __restrict__ W,
                                __nv_bfloat16* __restrict__ Th,
                                __nv_bfloat16* __restrict__ Tl, int K, int N)
{
    __shared__ float t[32][33];
    int n = blockIdx.x * 32 + threadIdx.x;
    int k = blockIdx.y * 32 + threadIdx.y;
    t[threadIdx.y][threadIdx.x] = W[(size_t)k * N + n];
    __syncthreads();
    int kk = blockIdx.y * 32 + threadIdx.x;
    int nn = blockIdx.x * 32 + threadIdx.y;
    float v = t[threadIdx.x][threadIdx.y];
    __nv_bfloat16 hv = __float2bfloat16(v);
    Th[(size_t)nn * K + kk] = hv;
    Tl[(size_t)nn * K + kk] = __float2bfloat16(v - __bfloat162float(hv));
}

// ============================================================
// Attention (fp32x2), V-split x2, row-split x2:
// grid 512 blocks of 128 threads; block idx = (((b*16+h)*2+rh)*2+vs).
// Unnormalized softmax partials written to g_part/g_lsum.
// ============================================================
__global__ __launch_bounds__(128) void attn2(
    const float* __restrict__ q, const float* __restrict__ kmat,
    const float* __restrict__ vmat, float* __restrict__ part,
    float* __restrict__ lsums)
{
    __shared__ __align__(16) float ks[64 * 64];
    __shared__ __align__(16) float vs[64 * 64];

    const int idx = blockIdx.x;
    const int vsp = idx & 1;
    const int rh  = (idx >> 1) & 1;
    const int h   = (idx >> 2) & 15;
    const int b   = idx >> 6;
    const int p   = rh * 128 + threadIdx.x;
    const int tid = threadIdx.x;

    const float* qp = q + ((size_t)(b * NP + p) * NDM) + h * NDK;
    ull q2[32];
#pragma unroll
    for (int d = 0; d < 64; d += 4) {
        float4 t = *(const float4*)(qp + d);
        q2[d / 2]     = pack2(t.x, t.y);
        q2[d / 2 + 1] = pack2(t.z, t.w);
    }

    ull o2[32];
#pragma unroll
    for (int i = 0; i < 32; i++) o2[i] = 0ull;
    float lsum = 0.0f;

    const int vbeg = vsp * (NV / 2), vend = vbeg + NV / 2;
    for (int v0 = vbeg; v0 < vend; v0 += 64) {
#pragma unroll
        for (int i = 0; i < 8; i++) {
            int f4 = tid + i * 128;            // 0..1023
            int r  = f4 >> 4;
            int c4 = f4 & 15;
            size_t goff = (size_t)(v0 + r) * NDM + h * NDK + c4 * 4;
            ((float4*)ks)[f4] = *(const float4*)(kmat + goff);
            ((float4*)vs)[f4] = *(const float4*)(vmat + goff);
        }
        __syncthreads();

#pragma unroll 2
        for (int j = 0; j < 64; j++) {
            const ull* kr = (const ull*)(ks) + j * 32;
            ull s2a = 0ull, s2b = 0ull, s2c = 0ull, s2d = 0ull;
#pragma unroll
            for (int d2 = 0; d2 < 32; d2 += 4) {
                FMA2(s2a, q2[d2],     kr[d2]);
                FMA2(s2b, q2[d2 + 1], kr[d2 + 1]);
                FMA2(s2c, q2[d2 + 2], kr[d2 + 2]);
                FMA2(s2d, q2[d2 + 3], kr[d2 + 3]);
            }
            float2 ua = unpack2(s2a), ub = unpack2(s2b);
            float2 uc = unpack2(s2c), ud = unpack2(s2d);
            float s  = ((ua.x + ua.y) + (ub.x + ub.y)) +
                       ((uc.x + uc.y) + (ud.x + ud.y));
            float pe = __expf(s * (1.0f / 64.0f));
            lsum += pe;
            ull pe2 = pack2(pe, pe);
            const ull* vr = (const ull*)(vs) + j * 32;
#pragma unroll
            for (int d2 = 0; d2 < 32; d2++)
                FMA2(o2[d2], pe2, vr[d2]);
        }
        __syncthreads();
    }

    float* op = part + (size_t)vsp * NQ * NDM + ((size_t)(b * NP + p) * NDM) + h * NDK;
#pragma unroll
    for (int d2 = 0; d2 < 32; d2 += 2) {
        float2 x = unpack2(o2[d2]);
        float2 y = unpack2(o2[d2 + 1]);
        *(float4*)(op + d2 * 2) = make_float4(x.x, x.y, y.x, y.y);
    }
    lsums[(size_t)vsp * NQ * NH + (size_t)(b * NP + p) * NH + h] = lsum;
}

// combine the two V-split partials and emit bf16 hi/lo directly:
// m = (pA + pB) / (lA + lB);  mh = bf16(m); ml = bf16(m - mh)
__global__ __launch_bounds__(256) void attn_combine(
    const float* __restrict__ part, const float* __restrict__ lsums,
    __nv_bfloat162* __restrict__ mh, __nv_bfloat162* __restrict__ ml)
{
    int i = blockIdx.x * blockDim.x + threadIdx.x;    // float4 index
    if (i >= NQ * NDM / 4) return;
    int row = i >> 8;             // 256 float4 per row
    int h = (i & 255) >> 4;       // 16 float4 per head block
    float l = lsums[(size_t)row * NH + h] +
              lsums[(size_t)NQ * NH + (size_t)row * NH + h];
    float inv = 1.0f / l;
    float4 a = ((const float4*)part)[i];
    float4 b = ((const float4*)part)[(size_t)NQ * NDM / 4 + i];
    float4 v = make_float4((a.x + b.x) * inv, (a.y + b.y) * inv,
                           (a.z + b.z) * inv, (a.w + b.w) * inv);
    __nv_bfloat16 h0 = __float2bfloat16(v.x), h1 = __float2bfloat16(v.y);
    __nv_bfloat16 h2 = __float2bfloat16(v.z), h3 = __float2bfloat16(v.w);
    mh[2 * i]     = __halves2bfloat162(h0, h1);
    mh[2 * i + 1] = __halves2bfloat162(h2, h3);
    ml[2 * i]     = __halves2bfloat162(__float2bfloat16(v.x - __bfloat162float(h0)),
                                       __float2bfloat16(v.y - __bfloat162float(h1)));
    ml[2 * i + 1] = __halves2bfloat162(__float2bfloat16(v.z - __bfloat162float(h2)),
                                       __float2bfloat16(v.w - __bfloat162float(h3)));
}

// ============================================================
extern "C" void kernel_launch(void* const* d_in, const int* in_sizes, int n_in,
                              void* d_out, int out_size)
{
    const float* query = (const float*)d_in[0];
    const float* key   = (const float*)d_in[1];
    const float* value = (const float*)d_in[2];
    const float* Wq    = (const float*)d_in[3];
    const float* bq    = (const float*)d_in[4];
    const float* Wk    = (const float*)d_in[5];
    const float* bk    = (const float*)d_in[6];
    const float* Wv    = (const float*)d_in[7];
    const float* bv    = (const float*)d_in[8];
    const float* Wo    = (const float*)d_in[9];
    const float* bo    = (const float*)d_in[10];
    float* out = (float*)d_out;

    float *q_, *k_, *v_, *part_, *ls_;
    cudaGetSymbolAddress((void**)&q_, g_q);
    cudaGetSymbolAddress((void**)&k_, g_k);
    cudaGetSymbolAddress((void**)&v_, g_v);
    cudaGetSymbolAddress((void**)&part_, g_part);
    cudaGetSymbolAddress((void**)&ls_, g_lsum);

    __nv_bfloat16 *qh, *ql, *kh, *kl, *vh, *vl, *mh, *ml;
    __nv_bfloat16 *wqh, *wql, *wkh, *wkl, *wvh, *wvl, *woh, *wol;
    cudaGetSymbolAddress((void**)&qh, g_qryh);  cudaGetSymbolAddress((void**)&ql, g_qryl);
    cudaGetSymbolAddress((void**)&kh, g_keyh);  cudaGetSymbolAddress((void**)&kl, g_keyl);
    cudaGetSymbolAddress((void**)&vh, g_valh);  cudaGetSymbolAddress((void**)&vl, g_vall);
    cudaGetSymbolAddress((void**)&mh, g_maph);  cudaGetSymbolAddress((void**)&ml, g_mapl);
    cudaGetSymbolAddress((void**)&wqh, g_Wqh);  cudaGetSymbolAddress((void**)&wql, g_Wql);
    cudaGetSymbolAddress((void**)&wkh, g_Wkh);  cudaGetSymbolAddress((void**)&wkl, g_Wkl);
    cudaGetSymbolAddress((void**)&wvh, g_Wvh);  cudaGetSymbolAddress((void**)&wvl, g_Wvl);
    cudaGetSymbolAddress((void**)&woh, g_Woh);  cudaGetSymbolAddress((void**)&wol, g_Wol);

    cudaFuncSetAttribute(gemm_hmma, cudaFuncAttributeMaxDynamicSharedMemorySize, GSMEM);

    // --- operand prep: weight transposes + activation splits ---
    transpose_split<<<dim3(NDM / 32, NDM / 32), dim3(32, 32)>>>(Wq, wqh, wql, NDM, NDM);
    transpose_split<<<dim3(NDM / 32, NDL / 32), dim3(32, 32)>>>(Wk, wkh, wkl, NDL, NDM);
    transpose_split<<<dim3(NDM / 32, NDL / 32), dim3(32, 32)>>>(Wv, wvh, wvl, NDL, NDM);
    transpose_split<<<dim3(NDL / 32, NDM / 32), dim3(32, 32)>>>(Wo, woh, wol, NDM, NDL);
    {
        int n4 = NQ * NDM / 4;
        split4<<<(n4 + 255) / 256, 256>>>(query, (__nv_bfloat162*)qh, (__nv_bfloat162*)ql, n4);
    }
    {
        int n4 = NV * NDL / 4;
        split4<<<(n4 + 255) / 256, 256>>>(key,   (__nv_bfloat162*)kh, (__nv_bfloat162*)kl, n4);
        split4<<<(n4 + 255) / 256, 256>>>(value, (__nv_bfloat162*)vh, (__nv_bfloat162*)vl, n4);
    }

    // --- projections on HMMA tensor cores ---
    // q,k: 1-pass bf16 (errors enter only via softmax logits, damped by 1/64 scale)
    // v,o: 3-pass split (errors pass straight to output)
    gemm_hmma<<<dim3(NDM / 128, NQ / 128), 256, GSMEM>>>(qh, ql, wqh, wql, bq, q_, NQ, NDM, NDM, 1);
    gemm_hmma<<<dim3(NDM / 128, NV / 128), 256, GSMEM>>>(kh, kl, wkh, wkl, bk, k_, NV, NDM, NDL, 1);
    gemm_hmma<<<dim3(NDM / 128, NV / 128), 256, GSMEM>>>(vh, vl, wvh, wvl, bv, v_, NV, NDM, NDL, 3);

    // --- attention (V-split x2) ---
    attn2<<<NB * NH * 4, 128>>>(q_, k_, v_, part_, ls_);
    {
        int n4 = NQ * NDM / 4;
        attn_combine<<<(n4 + 255) / 256, 256>>>(part_, ls_, (__nv_bfloat162*)mh, (__nv_bfloat162*)ml);
    }

    // --- output projection ---
    gemm_hmma<<<dim3(NDL / 128, NQ / 128), 256, GSMEM>>>(mh, ml, woh, wol, bo, out, NQ, NDL, NDM, 3);
}